// round 2
// baseline (speedup 1.0000x reference)
#include <cuda_runtime.h>
#include <math.h>

#define NB 64
#define NS 4096
#define ND 256
#define SPLIT 8
#define CHUNK (NS / SPLIT)     // 512 rows per CTA
#define TILE 32
#define BLOCK 256

// Cross-CTA partial results (online-softmax state per (batch, split-chunk)).
// __device__ globals: allowed scratch (no runtime allocation).
__device__ float g_acc[NB * SPLIT * ND];
__device__ float g_m[NB * SPLIT];
__device__ float g_l[NB * SPLIT];

__global__ __launch_bounds__(BLOCK)
void att_pass1(const float* __restrict__ aspect,
               const float* __restrict__ memory,
               const float* __restrict__ W,
               const float* __restrict__ bias)
{
    const int b     = blockIdx.y;
    const int chunk = blockIdx.x;
    const int tid   = threadIdx.x;
    const int warp  = tid >> 5;
    const int lane  = tid & 31;

    __shared__ float sW[ND];                 // Wm
    __shared__ float s_tile[TILE * ND];      // 32 KB staging tile
    __shared__ float s_gi[TILE];
    __shared__ float s_red[8];

    // Wm into shared
    sW[tid] = W[tid];

    // a_b = aspect[b] . Wa + bias   (block reduction, result broadcast)
    float av = aspect[b * ND + tid] * W[ND + tid];
    #pragma unroll
    for (int o = 16; o; o >>= 1) av += __shfl_xor_sync(0xFFFFFFFFu, av, o);
    if (lane == 0) s_red[warp] = av;
    __syncthreads();
    float a_b = bias[0];
    #pragma unroll
    for (int w = 0; w < 8; w++) a_b += s_red[w];

    // Online softmax state; thread tid owns dim d = tid of acc.
    float m_run = -INFINITY;
    float l_run = 0.f;
    float acc   = 0.f;

    const float* memb = memory + ((size_t)b * NS + (size_t)chunk * CHUNK) * ND;

    for (int t0 = 0; t0 < CHUNK; t0 += TILE) {
        __syncthreads();  // previous tile fully consumed before overwrite

        // Stage TILE x ND floats: 2048 float4, 8 per thread, coalesced.
        const float4* src = (const float4*)(memb + (size_t)t0 * ND);
        float4*       dst = (float4*)s_tile;
        #pragma unroll
        for (int i = 0; i < 8; i++)
            dst[tid + i * BLOCK] = src[tid + i * BLOCK];
        __syncthreads();

        // gi for 32 rows: warp w -> rows [4w, 4w+4). Stride-32 smem reads: conflict-free.
        #pragma unroll
        for (int rr = 0; rr < 4; rr++) {
            const int r = warp * 4 + rr;
            float d = 0.f;
            #pragma unroll
            for (int k = 0; k < 8; k++) {
                const int c = lane + k * 32;
                d = fmaf(s_tile[r * ND + c], sW[c], d);
            }
            #pragma unroll
            for (int o = 16; o; o >>= 1) d += __shfl_xor_sync(0xFFFFFFFFu, d, o);
            if (lane == 0) s_gi[r] = tanhf(d + a_b);
        }
        __syncthreads();

        // Online softmax update (every thread keeps identical m/l; acc is per-dim).
        float tmax = m_run;
        #pragma unroll
        for (int r = 0; r < TILE; r++) tmax = fmaxf(tmax, s_gi[r]);
        const float scale = __expf(m_run - tmax);   // exp(-inf)=0 on first tile
        acc   *= scale;
        l_run *= scale;
        m_run  = tmax;

        #pragma unroll
        for (int r = 0; r < TILE; r++) {
            const float w = __expf(s_gi[r] - m_run);
            l_run += w;
            acc = fmaf(w, s_tile[r * ND + tid], acc);  // bank tid%32: conflict-free
        }
    }

    const int idx = b * SPLIT + chunk;
    g_acc[idx * ND + tid] = acc;
    if (tid == 0) { g_m[idx] = m_run; g_l[idx] = l_run; }
}

__global__ __launch_bounds__(BLOCK)
void att_pass2(float* __restrict__ out)
{
    const int b   = blockIdx.x;
    const int tid = threadIdx.x;

    float M = -INFINITY;
    #pragma unroll
    for (int i = 0; i < SPLIT; i++) M = fmaxf(M, g_m[b * SPLIT + i]);

    float num = 0.f, den = 0.f;
    #pragma unroll
    for (int i = 0; i < SPLIT; i++) {
        const float w = __expf(g_m[b * SPLIT + i] - M);
        den += w * g_l[b * SPLIT + i];
        num += w * g_acc[(b * SPLIT + i) * ND + tid];
    }
    out[b * ND + tid] = num / den;
}

extern "C" void kernel_launch(void* const* d_in, const int* in_sizes, int n_in,
                              void* d_out, int out_size)
{
    const float* aspect = (const float*)d_in[0];  // (64, 1, 256)
    const float* memory = (const float*)d_in[1];  // (64, 4096, 256)
    const float* W      = (const float*)d_in[2];  // (512, 1)
    const float* bias   = (const float*)d_in[3];  // (1,)
    float* out = (float*)d_out;                   // (64, 256)

    dim3 grid1(SPLIT, NB);
    att_pass1<<<grid1, BLOCK>>>(aspect, memory, W, bias);
    att_pass2<<<NB, BLOCK>>>(out);
}

// round 3
// speedup vs baseline: 1.2038x; 1.2038x over previous
#include <cuda_runtime.h>
#include <math.h>

#define NB 64
#define NS 4096
#define ND 256
#define SPLIT 32
#define CHUNK (NS / SPLIT)        // 128 rows per CTA
#define BLOCK 128
#define NWARP (BLOCK / 32)        // 4
#define RPW (CHUNK / NWARP)       // 32 rows per warp
#define RUN 4                     // rows per unrolled iteration

// Partial results per (batch, chunk). __device__ globals: legal scratch.
__device__ float g_num[NB * SPLIT * ND];
__device__ float g_den[NB * SPLIT];

__device__ __forceinline__ float tanh_fast(float x) {
    // tanh(x) = 1 - 2/(e^{2x}+1); safe at both extremes (inf -> 1, 0 -> -1)
    float e = __expf(2.0f * x);
    return 1.0f - __fdividef(2.0f, e + 1.0f);
}

__global__ __launch_bounds__(BLOCK)
void att_pass1(const float* __restrict__ aspect,
               const float* __restrict__ memory,
               const float* __restrict__ W,
               const float* __restrict__ bias)
{
    const int b     = blockIdx.y;
    const int chunk = blockIdx.x;
    const int tid   = threadIdx.x;
    const int warp  = tid >> 5;
    const int lane  = tid & 31;

    __shared__ float s_red[NWARP];
    __shared__ float s_acc[NWARP][ND];
    __shared__ float s_den[NWARP];

    // a_b = aspect[b] . Wa + bias  (two elems per thread, block reduce)
    float av = aspect[b * ND + tid]       * W[ND + tid]
             + aspect[b * ND + tid + 128] * W[ND + tid + 128];
    #pragma unroll
    for (int o = 16; o; o >>= 1) av += __shfl_xor_sync(0xFFFFFFFFu, av, o);
    if (lane == 0) s_red[warp] = av;
    __syncthreads();
    const float a_b = bias[0] + s_red[0] + s_red[1] + s_red[2] + s_red[3];

    // Wm slice for this lane's 8 dims
    const float4 w0 = *(const float4*)(W + lane * 8);
    const float4 w1 = *(const float4*)(W + lane * 8 + 4);

    // Base pointer: this warp's rows, this lane's 8 columns
    const float* rowp = memory
        + ((size_t)b * NS + (size_t)chunk * CHUNK + (size_t)warp * RPW) * ND
        + lane * 8;

    float acc0 = 0.f, acc1 = 0.f, acc2 = 0.f, acc3 = 0.f;
    float acc4 = 0.f, acc5 = 0.f, acc6 = 0.f, acc7 = 0.f;
    float den = 0.f;

    for (int r0 = 0; r0 < RPW; r0 += RUN) {
        float4 va[RUN], vb[RUN];
        #pragma unroll
        for (int r = 0; r < RUN; r++) {
            const float* p = rowp + (size_t)(r0 + r) * ND;
            va[r] = *(const float4*)(p);
            vb[r] = *(const float4*)(p + 4);
        }

        float d[RUN];
        #pragma unroll
        for (int r = 0; r < RUN; r++) {
            float s = va[r].x * w0.x;
            s = fmaf(va[r].y, w0.y, s);
            s = fmaf(va[r].z, w0.z, s);
            s = fmaf(va[r].w, w0.w, s);
            s = fmaf(vb[r].x, w1.x, s);
            s = fmaf(vb[r].y, w1.y, s);
            s = fmaf(vb[r].z, w1.z, s);
            s = fmaf(vb[r].w, w1.w, s);
            d[r] = s;
        }

        // 4 interleaved bfly reductions (latency overlaps)
        #pragma unroll
        for (int o = 16; o; o >>= 1) {
            #pragma unroll
            for (int r = 0; r < RUN; r++)
                d[r] += __shfl_xor_sync(0xFFFFFFFFu, d[r], o);
        }

        #pragma unroll
        for (int r = 0; r < RUN; r++) {
            const float gi = tanh_fast(d[r] + a_b);
            const float w  = __expf(gi - 1.0f);   // fixed max=1: gi in [-1,1]
            den += w;
            acc0 = fmaf(w, va[r].x, acc0);
            acc1 = fmaf(w, va[r].y, acc1);
            acc2 = fmaf(w, va[r].z, acc2);
            acc3 = fmaf(w, va[r].w, acc3);
            acc4 = fmaf(w, vb[r].x, acc4);
            acc5 = fmaf(w, vb[r].y, acc5);
            acc6 = fmaf(w, vb[r].z, acc6);
            acc7 = fmaf(w, vb[r].w, acc7);
        }
    }

    // Per-warp partials -> smem
    float4* sa = (float4*)&s_acc[warp][lane * 8];
    sa[0] = make_float4(acc0, acc1, acc2, acc3);
    sa[1] = make_float4(acc4, acc5, acc6, acc7);
    if (lane == 0) s_den[warp] = den;
    __syncthreads();

    // Combine 4 warps; 128 threads cover 256 dims (2 each)
    const int idx = b * SPLIT + chunk;
    #pragma unroll
    for (int k = 0; k < 2; k++) {
        const int d = tid + k * BLOCK;
        g_num[(size_t)idx * ND + d] =
            s_acc[0][d] + s_acc[1][d] + s_acc[2][d] + s_acc[3][d];
    }
    if (tid == 0)
        g_den[idx] = s_den[0] + s_den[1] + s_den[2] + s_den[3];
}

__global__ __launch_bounds__(256)
void att_pass2(float* __restrict__ out)
{
    const int b   = blockIdx.x;
    const int tid = threadIdx.x;

    float num = 0.f, den = 0.f;
    #pragma unroll
    for (int i = 0; i < SPLIT; i++) {
        num += g_num[(size_t)(b * SPLIT + i) * ND + tid];
        den += g_den[b * SPLIT + i];
    }
    out[b * ND + tid] = __fdividef(num, den);
}

extern "C" void kernel_launch(void* const* d_in, const int* in_sizes, int n_in,
                              void* d_out, int out_size)
{
    const float* aspect = (const float*)d_in[0];  // (64, 1, 256)
    const float* memory = (const float*)d_in[1];  // (64, 4096, 256)
    const float* W      = (const float*)d_in[2];  // (512, 1)
    const float* bias   = (const float*)d_in[3];  // (1,)
    float* out = (float*)d_out;                   // (64, 256)

    dim3 grid1(SPLIT, NB);
    att_pass1<<<grid1, BLOCK>>>(aspect, memory, W, bias);
    att_pass2<<<NB, 256>>>(out);
}